// round 15
// baseline (speedup 1.0000x reference)
#include <cuda_runtime.h>

// DerivativeDILATEloss: soft-DTW(gamma=0.01), D[i,j]=(dy_i-dx_j)^2, B=64, n=511.
//
// Round 15: 2 CTAs per batch via L2-pipelined edge. CTA A (even) = rows
// 0..255, CTA B (odd) = rows 256..511. Each CTA: NT=256, W=1 row/thread,
// 8 warps (2/SMSP) -> per-SMSP MUFU floor 48 cyc/step (half of R10).
// Intra-CTA: proven free-running smem mailboxes. Edge row255->row256:
// global float2 ring + release/acquire counter, double-buffered loads
// (data prefetched one 4-step block ahead; counter load software-pipelined).
// Direct 3-ex2 softmin in (m,s) form, dx padding, fused last-CTA reduction.

#define NSEQ   511
#define NBATCH 64
#define NT     256
#define INFV   1.0e9f
#define PADV   1.0e4f
#define INVK   0.0069314718055994531f  // ln(2)/100
#define SQRTK  12.011224298677374f     // sqrt(100/ln2)

// local bbuf float2[8][1024] = 64KB; padded to 120KB to force 1 CTA/SM
#define SMEM_BYTES (120 * 1024)

__device__ __forceinline__ float ex2f(float x){float r;asm("ex2.approx.f32 %0,%1;":"=f"(r):"f"(x));return r;}
__device__ __forceinline__ float lg2f(float x){float r;asm("lg2.approx.f32 %0,%1;":"=f"(r):"f"(x));return r;}
__device__ __forceinline__ unsigned s2u(const void* p){return (unsigned)__cvta_generic_to_shared(p);}
template<int OFF>
__device__ __forceinline__ void sts_pair_pred_off(unsigned a, float m, float s, int p){
    asm volatile("{.reg .pred q; setp.ne.u32 q,%0,0; @q st.shared.v2.f32 [%1+%4],{%2,%3};}"
                 ::"r"(p),"r"(a),"f"(m),"f"(s),"n"(OFF):"memory");
}
__device__ __forceinline__ void strel_pred(unsigned a, int v, int p){
    asm volatile("{.reg .pred q; setp.ne.u32 q,%0,0; @q st.release.cta.shared.b32 [%1],%2;}"
                 ::"r"(p),"r"(a),"r"(v):"memory");
}
__device__ __forceinline__ int ld_acq(unsigned a){
    int v; asm volatile("ld.acquire.cta.shared.b32 %0,[%1];":"=r"(v):"r"(a):"memory"); return v;
}
__device__ __forceinline__ int ld_acq_gpu(const int* p){
    int v; asm volatile("ld.acquire.gpu.global.b32 %0,[%1];":"=r"(v):"l"(p):"memory"); return v;
}
__device__ __forceinline__ void strel_gpu_pred(int* p, int v, int pr){
    asm volatile("{.reg .pred q; setp.ne.u32 q,%0,0; @q st.release.gpu.global.b32 [%1],%2;}"
                 ::"r"(pr),"l"(p),"r"(v):"memory");
}
__device__ __forceinline__ void stg_v4_pred(float2* p, float a, float bb, float c, float dd, int pr){
    asm volatile("{.reg .pred q; setp.ne.u32 q,%0,0; @q st.global.v4.f32 [%1],{%2,%3,%4,%5};}"
                 ::"r"(pr),"l"(p),"f"(a),"f"(bb),"f"(c),"f"(dd):"memory");
}

__device__ float2 g_edge[NBATCH][1024];   // zero-init; slot d = A row-255 (m,s) @ diag d
__device__ int    g_cnt[NBATCH];          // monotone published diag
__device__ float  g_partial[NBATCH];
__device__ int    g_done = 0;

__global__ __launch_bounds__(NT, 1)
void sdtw_kernel(const float* __restrict__ input,
                 const float* __restrict__ target,
                 float* __restrict__ out)
{
    __shared__ float sdxp[1536];   // padded scaled dx, logical base 512
    __shared__ int   cnt[16];      // [0..6] local producers, [15] sentinel
    __shared__ int   slast;
    extern __shared__ float2 bbuf[];   // [8][1024]; row 7 = dummy

    const int t = threadIdx.x, w = t >> 5, lane = t & 31;
    const int b     = blockIdx.x >> 1;
    const int roleB = blockIdx.x & 1;

    const float* in_b = input  + b * 512;
    const float* tg_b = target + b * 512;

    #pragma unroll
    for (int rep = 0; rep < 6; ++rep) {
        int idx = t + rep * NT, q = idx - 512;
        float v = PADV;
        if (q >= 0 && q < NSEQ) v = (in_b[q + 1] - in_b[q]) * SQRTK;
        sdxp[idx] = v;
    }
    #pragma unroll
    for (int rep = 0; rep < 4; ++rep)          // dummy row 7: (INF, 1)
        bbuf[7 * 1024 + t + rep * NT] = make_float2(INFV, 1.0f);
    if (t < 16) cnt[t] = (t == 15) ? 0x7FFFFFFF : 0;
    if (t == 0) slast = 0;

    const int i = roleB * 256 + t;             // owned global row
    const float dyr = (i >= 1) ? (tg_b[i] - tg_b[i - 1]) * SQRTK : 0.0f;
    __syncthreads();   // only CTA-wide barrier

    // state (m,s): value = m - log2(s)
    float r1m = INFV, r1s = 1.0f;              // own row @ diag d-1
    float am  = (i == 1) ? 0.0f : INFV;        // row i-1 @ diag d-2 (R[0,0] seed)
    float as_ = 1.0f;
    float mbm = INFV, mbs = 1.0f;              // lane-0 boundary @ diag d-1
    const float* dxp = sdxp + 512 - i - 1;     // dxp[d] = scaled dx[j-1]
    float dxv = dxp[2];

    const float2* subrow = bbuf + ((w == 0) ? 7 : (w - 1)) * 1024;
    unsigned pub_a  = s2u(&bbuf[((w < 7) ? w : 0) * 1024]) + 2u * 8u;  // slot d0=2
    unsigned cnt_a  = s2u(&cnt[w]);
    unsigned cntp_a = s2u(&cnt[(w == 0) ? 15 : (w - 1)]);
    const int ispub = (lane == 31 && w < 7) ? 1 : 0;
    const int p31   = (lane == 31) ? 1 : 0;
    const bool ea = (!roleB) && (w == 7);      // edge producer warp (A row 255)
    const bool ec = roleB && (w == 0);         // edge consumer warp (B row 256 area)
    int cc = 0;

    // edge consumer pipeline state
    float4 cur0 = make_float4(INFV,1.0f,INFV,1.0f);
    float4 cur1 = cur0, nxt0 = cur0, nxt1 = cur0;
    int ccok = 0, cc_pf = 0;
    if (ec) {
        do { ccok = ld_acq_gpu(&g_cnt[b]); } while (ccok < 25);   // A gains ~5-block lead
        const float4* eb = (const float4*)&g_edge[b][2];
        cur0 = eb[0]; cur1 = eb[1];            // slots 2..5
        cc_pf = ccok;
    }

    float pm0, ps0, pm1, ps1, pm2, ps2, pm3, ps3;

    #pragma unroll 1
    for (int d0 = 2; d0 <= 1018; d0 += 4) {
        const int need = d0 + 3;
        if (cc < need) { do { cc = ld_acq(cntp_a); } while (cc < need); }

        float4 bl0 = *reinterpret_cast<const float4*>(subrow + d0);
        float4 bl1 = *reinterpret_cast<const float4*>(subrow + d0 + 2);

        if (ec) {   // warp-uniform: pipelined counter + double-buffered data
            if (cc_pf > ccok) ccok = cc_pf;
            cc_pf = ld_acq_gpu(&g_cnt[b]);                 // consume next block
            const int neednx = (d0 <= 1014) ? (d0 + 7) : 1021;
            while (ccok < neednx) { ccok = ld_acq_gpu(&g_cnt[b]); }
            const float4* eb = (const float4*)&g_edge[b][(d0 <= 1014) ? (d0 + 4) : 2];
            nxt0 = eb[0]; nxt1 = eb[1];                    // slots for next block
            bl0 = cur0; bl1 = cur1;                        // slots d0..d0+3
        }

        #pragma unroll
        for (int u = 0; u < 4; ++u) {
            const float shm = __shfl_up_sync(0xFFFFFFFFu, r1m, 1);
            const float shs = __shfl_up_sync(0xFFFFFFFFu, r1s, 1);
            const float um = (lane == 0) ? mbm : shm;
            const float us = (lane == 0) ? mbs : shs;

            const float mnm = fminf(fminf(am, um), r1m);
            const float x1 = ex2f(mnm - am);
            const float x2 = ex2f(mnm - um);
            const float x3 = ex2f(mnm - r1m);
            float ns = fmaf(as_, x1, fmaf(us, x2, r1s * x3));
            const float dv = dyr - dxv;
            float nm = fmaf(dv, dv, mnm);

            if (u == 3) {   // exact power-of-2 renorm of s into m
                unsigned sb = __float_as_uint(ns);
                int e = (int)(sb >> 23) - 127;
                ns = __uint_as_float((sb & 0x007FFFFFu) | 0x3F800000u);
                nm -= (float)e;
            }

            if (u == 0) { pm0 = nm; ps0 = ns; sts_pair_pred_off<0 >(pub_a, nm, ns, ispub); }
            if (u == 1) { pm1 = nm; ps1 = ns; sts_pair_pred_off<8 >(pub_a, nm, ns, ispub); }
            if (u == 2) { pm2 = nm; ps2 = ns; sts_pair_pred_off<16>(pub_a, nm, ns, ispub); }
            if (u == 3) { pm3 = nm; ps3 = ns; sts_pair_pred_off<24>(pub_a, nm, ns, ispub);
                          strel_pred(cnt_a, d0 + 3, ispub); }

            am = um; as_ = us;
            r1m = nm; r1s = ns;
            dxv = dxp[d0 + u + 1];
            mbm = (u == 0) ? bl0.x : (u == 1) ? bl0.z : (u == 2) ? bl1.x : bl1.z;
            mbs = (u == 0) ? bl0.y : (u == 1) ? bl0.w : (u == 2) ? bl1.y : bl1.w;
        }
        pub_a += 32u;

        if (ea) {   // warp-uniform: edge producer publishes block to L2
            stg_v4_pred(&g_edge[b][d0],     pm0, ps0, pm1, ps1, p31);
            stg_v4_pred(&g_edge[b][d0 + 2], pm2, ps2, pm3, ps3, p31);
            strel_gpu_pred(&g_cnt[b], need, p31);
        }
        if (ec) { cur0 = nxt0; cur1 = nxt1; }
    }

    // tail step d = 1022 (no publish/poll)
    float resm, ress;
    {
        const float shm = __shfl_up_sync(0xFFFFFFFFu, r1m, 1);
        const float shs = __shfl_up_sync(0xFFFFFFFFu, r1s, 1);
        const float um = (lane == 0) ? mbm : shm;
        const float us = (lane == 0) ? mbs : shs;
        const float mnm = fminf(fminf(am, um), r1m);
        const float x1 = ex2f(mnm - am);
        const float x2 = ex2f(mnm - um);
        const float x3 = ex2f(mnm - r1m);
        ress = fmaf(as_, x1, fmaf(us, x2, r1s * x3));
        const float dv = dyr - dxv;
        resm = fmaf(dv, dv, mnm);
    }

    // fused reduction: B CTAs' row 511 writes partial; last of 64 reduces
    if (roleB && t == NT - 1) {
        g_partial[b] = (resm - lg2f(ress)) * INVK;
        __threadfence();
        int prev = atomicAdd(&g_done, 1);
        slast = (prev == NBATCH - 1) ? 1 : 0;
    }
    __syncthreads();
    if (slast && t < 32) {
        __threadfence();
        float s = g_partial[t] + g_partial[t + 32];
        #pragma unroll
        for (int o = 16; o > 0; o >>= 1)
            s += __shfl_down_sync(0xFFFFFFFFu, s, o);
        if (t == 0) { out[0] = s * (1.0f / (float)NBATCH); g_done = 0; }
    }
}

extern "C" void kernel_launch(void* const* d_in, const int* in_sizes, int n_in,
                              void* d_out, int out_size)
{
    const float* input  = (const float*)d_in[0];
    const float* target = (const float*)d_in[1];
    float* out = (float*)d_out;

    cudaFuncSetAttribute(sdtw_kernel,
                         cudaFuncAttributeMaxDynamicSharedMemorySize, SMEM_BYTES);
    sdtw_kernel<<<2 * NBATCH, NT, SMEM_BYTES>>>(input, target, out);
}

// round 16
// speedup vs baseline: 2.9269x; 2.9269x over previous
#include <cuda_runtime.h>

// DerivativeDILATEloss: soft-DTW(gamma=0.01), D[i,j]=(dy_i-dx_j)^2, B=64, n=511.
//
// Round 16: R10 engine + band-restricted per-warp loops. Warp w (rows
// 64w..64w+63) only iterates blocks d0 in [64w-2, 64w+574] (573 valid steps
// of 1021); out-of-band diagonals are never computed (cold-start state = INF
// init). Consumer reads/polls clamped to producer's published range (exact
// coverage by construction). W=2 rows/thread, 256 thr, direct 3-ex2 softmin
// in (m,s) form, free-running mailboxes, dx padding, fused reduction.

#define NSEQ   511
#define NBATCH 64
#define NT     256
#define INFV   1.0e9f
#define PADV   1.0e4f
#define INVK   0.0069314718055994531f  // ln(2)/100
#define SQRTK  12.011224298677374f     // sqrt(100/ln2)

// dynamic smem: float2 bbuf[8][1024] (rows 0..6 producers, row 7 dummy)
#define SMEM_BYTES (8 * 1024 * 8)

__device__ __forceinline__ float ex2f(float x){float r;asm("ex2.approx.f32 %0,%1;":"=f"(r):"f"(x));return r;}
__device__ __forceinline__ float lg2f(float x){float r;asm("lg2.approx.f32 %0,%1;":"=f"(r):"f"(x));return r;}
__device__ __forceinline__ unsigned s2u(const void* p){return (unsigned)__cvta_generic_to_shared(p);}
template<int OFF>
__device__ __forceinline__ void sts_pair_pred_off(unsigned a, float m, float s, int p){
    asm volatile("{.reg .pred q; setp.ne.u32 q,%0,0; @q st.shared.v2.f32 [%1+%4],{%2,%3};}"
                 ::"r"(p),"r"(a),"f"(m),"f"(s),"n"(OFF):"memory");
}
__device__ __forceinline__ void strel_pred(unsigned a, int v, int p){
    asm volatile("{.reg .pred q; setp.ne.u32 q,%0,0; @q st.release.cta.shared.b32 [%1],%2;}"
                 ::"r"(p),"r"(a),"r"(v):"memory");
}
__device__ __forceinline__ int ld_acq(unsigned a){
    int v; asm volatile("ld.acquire.cta.shared.b32 %0,[%1];":"=r"(v):"r"(a):"memory"); return v;
}

__device__ float g_partial[NBATCH];
__device__ int   g_done = 0;

// one cell, (m,s) form (value = m - log2 s), direct 3-ex2 softmin.
#define CELL(NM, NS, AM, AS, EM, ES, CM, CS, DY, DX)                         \
    {                                                                        \
        const float mnm = fminf(fminf((AM), (EM)), (CM));                    \
        const float x1 = ex2f(mnm - (AM));                                   \
        const float x2 = ex2f(mnm - (EM));                                   \
        const float x3 = ex2f(mnm - (CM));                                   \
        NS = fmaf((AS), x1, fmaf((ES), x2, (CS) * x3));                      \
        const float dv = (DY) - (DX);                                        \
        NM = fmaf(dv, dv, mnm);                                              \
    }

__global__ __launch_bounds__(NT, 1)
void sdtw_kernel(const float* __restrict__ input,
                 const float* __restrict__ target,
                 float* __restrict__ out)
{
    __shared__ float sdxp[1536];   // padded scaled dx, logical base 512
    __shared__ int   cnt[16];      // [0..6] producers, [15] = +inf sentinel
    __shared__ int   slast;
    extern __shared__ float2 bbuf[];   // [8][1024]

    const int b = blockIdx.x, t = threadIdx.x, w = t >> 5, lane = t & 31;
    const float* in_b = input  + b * 512;
    const float* tg_b = target + b * 512;

    #pragma unroll
    for (int rep = 0; rep < 6; ++rep) {
        int idx = t + rep * NT, q = idx - 512;
        float v = PADV;
        if (q >= 0 && q < NSEQ) v = (in_b[q + 1] - in_b[q]) * SQRTK;
        sdxp[idx] = v;
    }
    #pragma unroll
    for (int rep = 0; rep < 4; ++rep)          // dummy row 7: (INF, 1)
        bbuf[7 * 1024 + t + rep * NT] = make_float2(INFV, 1.0f);
    if (t < 16) cnt[t] = (t == 15) ? 0x7FFFFFFF : 0;
    if (t == 0) slast = 0;

    const int i0 = 2 * t;                      // rows i0, i0+1 (warp w: 64w..64w+63)
    float dyr0, dyr1;
    dyr0 = (i0 >= 1) ? (tg_b[i0]     - tg_b[i0 - 1]) * SQRTK : 0.0f;
    dyr1 =             (tg_b[i0 + 1] - tg_b[i0])     * SQRTK;
    __syncthreads();   // only CTA-wide barrier

    // per-warp band: blocks d0 in [lo, hi], step 4 (all d0 == 2 mod 4)
    const int lo = (w == 0) ? 2 : (64 * w - 2);
    const int hi = (w == 7) ? 1018 : (64 * w + 574);
    const int clampv = 64 * w + 510;           // max slot base readable
    const int cmax   = 64 * w + 513;           // producer's final counter

    // state (m,s): value = m - log2(s); cold start at d0 = lo is all-INF
    float r1m0 = INFV, r1s0 = 1.0f, r1m1 = INFV, r1s1 = 1.0f;
    float r2m0 = INFV, r2s0 = 1.0f;
    if (t == 0) r2m0 = 0.0f;                   // R[0,0] = 0 (w=0, lo=2)
    float tn2m = INFV, tn2s = 1.0f;            // row i0-1 @ diag d-2
    float mbm  = INFV, mbs  = 1.0f;            // lane-0 boundary @ diag d-1
    float dxw0 = sdxp[512 + lo - i0 - 1];      // dx for row i0   @ d=lo
    float dxw1 = sdxp[512 + lo - i0 - 2];      // dx for row i0+1 @ d=lo

    const float2* subrow = bbuf + ((w == 0) ? 7 : (w - 1)) * 1024;
    unsigned pub_a  = s2u(&bbuf[((w < 7) ? w : 0) * 1024]) + (unsigned)lo * 8u;
    unsigned cnt_a  = s2u(&cnt[w]);
    unsigned cntp_a = s2u(&cnt[(w == 0) ? 15 : (w - 1)]);
    const int ispub = (lane == 31 && w < 7) ? 1 : 0;
    int cc = 0;
    const float* dxsrc = sdxp + 512 - i0;

    #pragma unroll 1
    for (int d0 = lo; d0 <= hi; d0 += 4) {
        const int need = min(d0 + 3, cmax);
        if (cc < need) { do { cc = ld_acq(cntp_a); } while (cc < need); }

        // batched boundary fetch (clamped to producer's published range)
        const int dc = min(d0, clampv);
        const float4 bl0 = *reinterpret_cast<const float4*>(subrow + dc);
        const float4 bl1 = *reinterpret_cast<const float4*>(subrow + dc + 2);

        #pragma unroll
        for (int u = 0; u < 4; ++u) {
            const int d = d0 + u;
            const float shm = __shfl_up_sync(0xFFFFFFFFu, r1m1, 1);
            const float shs = __shfl_up_sync(0xFFFFFFFFu, r1s1, 1);
            const float um = (lane == 0) ? mbm : shm;
            const float us = (lane == 0) ? mbs : shs;

            float nm0, ns0, nm1, ns1;
            CELL(nm0, ns0, tn2m, tn2s, um,   us,   r1m0, r1s0, dyr0, dxw0)
            CELL(nm1, ns1, r2m0, r2s0, r1m0, r1s0, r1m1, r1s1, dyr1, dxw1)

            if (u == 3) {   // exact power-of-2 renorm of s into m
                unsigned sb0 = __float_as_uint(ns0);
                int e0 = (int)(sb0 >> 23) - 127;
                ns0 = __uint_as_float((sb0 & 0x007FFFFFu) | 0x3F800000u);
                nm0 -= (float)e0;
                unsigned sb1 = __float_as_uint(ns1);
                int e1 = (int)(sb1 >> 23) - 127;
                ns1 = __uint_as_float((sb1 & 0x007FFFFFu) | 0x3F800000u);
                nm1 -= (float)e1;
            }

            if (u == 0) sts_pair_pred_off<0 >(pub_a, nm1, ns1, ispub);
            if (u == 1) sts_pair_pred_off<8 >(pub_a, nm1, ns1, ispub);
            if (u == 2) sts_pair_pred_off<16>(pub_a, nm1, ns1, ispub);
            if (u == 3) sts_pair_pred_off<24>(pub_a, nm1, ns1, ispub);
            if (u == 3) strel_pred(cnt_a, d, ispub);

            tn2m = um;  tn2s = us;
            r2m0 = r1m0; r2s0 = r1s0;
            r1m0 = nm0;  r1s0 = ns0;  r1m1 = nm1;  r1s1 = ns1;
            dxw1 = dxw0;
            dxw0 = dxsrc[d];                               // dx for step d+1
            mbm = (u == 0) ? bl0.x : (u == 1) ? bl0.z : (u == 2) ? bl1.x : bl1.z;
            mbs = (u == 0) ? bl0.y : (u == 1) ? bl0.w : (u == 2) ? bl1.y : bl1.w;
        }
        pub_a += 32u;
    }

    // tail step d = 1022 — only warp 7 (row 511 result)
    if (w == 7) {
        const float shm = __shfl_up_sync(0xFFFFFFFFu, r1m1, 1);
        const float shs = __shfl_up_sync(0xFFFFFFFFu, r1s1, 1);
        const float um = (lane == 0) ? mbm : shm;
        const float us = (lane == 0) ? mbs : shs;
        float nm0, ns0, nm1, ns1;
        CELL(nm0, ns0, tn2m, tn2s, um,   us,   r1m0, r1s0, dyr0, dxw0)
        CELL(nm1, ns1, r2m0, r2s0, r1m0, r1s0, r1m1, r1s1, dyr1, dxw1)
        (void)nm0; (void)ns0;

        if (t == NT - 1) {                      // row 511 holds R[511,511]
            g_partial[b] = (nm1 - lg2f(ns1)) * INVK;
            __threadfence();
            int prev = atomicAdd(&g_done, 1);
            slast = (prev == NBATCH - 1) ? 1 : 0;
        }
    }
    __syncthreads();
    if (slast && t < 32) {
        __threadfence();
        float s = g_partial[t] + g_partial[t + 32];
        #pragma unroll
        for (int o = 16; o > 0; o >>= 1)
            s += __shfl_down_sync(0xFFFFFFFFu, s, o);
        if (t == 0) { out[0] = s * (1.0f / (float)NBATCH); g_done = 0; }
    }
}

extern "C" void kernel_launch(void* const* d_in, const int* in_sizes, int n_in,
                              void* d_out, int out_size)
{
    const float* input  = (const float*)d_in[0];
    const float* target = (const float*)d_in[1];
    float* out = (float*)d_out;

    cudaFuncSetAttribute(sdtw_kernel,
                         cudaFuncAttributeMaxDynamicSharedMemorySize, SMEM_BYTES);
    sdtw_kernel<<<NBATCH, NT, SMEM_BYTES>>>(input, target, out);
}

// round 17
// speedup vs baseline: 3.0411x; 1.0390x over previous
#include <cuda_runtime.h>

// DerivativeDILATEloss: soft-DTW(gamma=0.01), D[i,j]=(dy_i-dx_j)^2, B=64, n=511.
//
// Round 17: R16 (banded W=2 engine) + latency-shortened frontier step:
//  - CELL1 (shfl-independent) computed FIRST; shfls of its pre-renorm output
//    issued immediately, hidden under CELL0. (Pre-renorm shfl is exact: the
//    (m,s) value m-log2(s) is representation-invariant.)
//  - dx prefetched per 4-step block via 2x LDS.64 (no LDS on the step chain).
// Direct 3-ex2 softmin in (m,s) form, free-running mailboxes, band-restricted
// per-warp loops, dx padding, fused last-CTA reduction.

#define NSEQ   511
#define NBATCH 64
#define NT     256
#define INFV   1.0e9f
#define PADV   1.0e4f
#define INVK   0.0069314718055994531f  // ln(2)/100
#define SQRTK  12.011224298677374f     // sqrt(100/ln2)

// dynamic smem: float2 bbuf[8][1024] (rows 0..6 producers, row 7 dummy)
#define SMEM_BYTES (8 * 1024 * 8)

__device__ __forceinline__ float ex2f(float x){float r;asm("ex2.approx.f32 %0,%1;":"=f"(r):"f"(x));return r;}
__device__ __forceinline__ float lg2f(float x){float r;asm("lg2.approx.f32 %0,%1;":"=f"(r):"f"(x));return r;}
__device__ __forceinline__ unsigned s2u(const void* p){return (unsigned)__cvta_generic_to_shared(p);}
template<int OFF>
__device__ __forceinline__ void sts_pair_pred_off(unsigned a, float m, float s, int p){
    asm volatile("{.reg .pred q; setp.ne.u32 q,%0,0; @q st.shared.v2.f32 [%1+%4],{%2,%3};}"
                 ::"r"(p),"r"(a),"f"(m),"f"(s),"n"(OFF):"memory");
}
__device__ __forceinline__ void strel_pred(unsigned a, int v, int p){
    asm volatile("{.reg .pred q; setp.ne.u32 q,%0,0; @q st.release.cta.shared.b32 [%1],%2;}"
                 ::"r"(p),"r"(a),"r"(v):"memory");
}
__device__ __forceinline__ int ld_acq(unsigned a){
    int v; asm volatile("ld.acquire.cta.shared.b32 %0,[%1];":"=r"(v):"r"(a):"memory"); return v;
}

__device__ float g_partial[NBATCH];
__device__ int   g_done = 0;

// one cell, (m,s) form (value = m - log2 s), direct 3-ex2 softmin.
#define CELL(NM, NS, AM, AS, EM, ES, CM, CS, DY, DX)                         \
    {                                                                        \
        const float mnm = fminf(fminf((AM), (EM)), (CM));                    \
        const float x1 = ex2f(mnm - (AM));                                   \
        const float x2 = ex2f(mnm - (EM));                                   \
        const float x3 = ex2f(mnm - (CM));                                   \
        NS = fmaf((AS), x1, fmaf((ES), x2, (CS) * x3));                      \
        const float dv = (DY) - (DX);                                        \
        NM = fmaf(dv, dv, mnm);                                              \
    }

__global__ __launch_bounds__(NT, 1)
void sdtw_kernel(const float* __restrict__ input,
                 const float* __restrict__ target,
                 float* __restrict__ out)
{
    __shared__ float sdxp[1536];   // padded scaled dx, logical base 512
    __shared__ int   cnt[16];      // [0..6] producers, [15] = +inf sentinel
    __shared__ int   slast;
    extern __shared__ float2 bbuf[];   // [8][1024]

    const int b = blockIdx.x, t = threadIdx.x, w = t >> 5, lane = t & 31;
    const float* in_b = input  + b * 512;
    const float* tg_b = target + b * 512;

    #pragma unroll
    for (int rep = 0; rep < 6; ++rep) {
        int idx = t + rep * NT, q = idx - 512;
        float v = PADV;
        if (q >= 0 && q < NSEQ) v = (in_b[q + 1] - in_b[q]) * SQRTK;
        sdxp[idx] = v;
    }
    #pragma unroll
    for (int rep = 0; rep < 4; ++rep)          // dummy row 7: (INF, 1)
        bbuf[7 * 1024 + t + rep * NT] = make_float2(INFV, 1.0f);
    if (t < 16) cnt[t] = (t == 15) ? 0x7FFFFFFF : 0;
    if (t == 0) slast = 0;

    const int i0 = 2 * t;                      // rows i0, i0+1 (warp w: 64w..64w+63)
    float dyr0, dyr1;
    dyr0 = (i0 >= 1) ? (tg_b[i0]     - tg_b[i0 - 1]) * SQRTK : 0.0f;
    dyr1 =             (tg_b[i0 + 1] - tg_b[i0])     * SQRTK;
    __syncthreads();   // only CTA-wide barrier

    // per-warp band: blocks d0 in [lo, hi], step 4 (all d0 == 2 mod 4)
    const int lo = (w == 0) ? 2 : (64 * w - 2);
    const int hi = (w == 7) ? 1018 : (64 * w + 574);
    const int clampv = 64 * w + 510;           // max slot base readable
    const int cmax   = 64 * w + 513;           // producer's final counter

    // state (m,s): value = m - log2(s); cold start at d0 = lo is all-INF
    float r1m0 = INFV, r1s0 = 1.0f, r1m1 = INFV, r1s1 = 1.0f;
    float r2m0 = INFV, r2s0 = 1.0f;
    if (t == 0) r2m0 = 0.0f;                   // R[0,0] = 0 (w=0, lo=2)
    float tn2m = INFV, tn2s = 1.0f;            // row i0-1 @ diag d-2
    float mbm  = INFV, mbs  = 1.0f;            // lane-0 boundary @ diag d-1
    float dxw0 = sdxp[512 + lo - i0 - 1];      // dx for row i0   @ d=lo
    float dxw1 = sdxp[512 + lo - i0 - 2];      // dx for row i0+1 @ d=lo

    const float2* subrow = bbuf + ((w == 0) ? 7 : (w - 1)) * 1024;
    unsigned pub_a  = s2u(&bbuf[((w < 7) ? w : 0) * 1024]) + (unsigned)lo * 8u;
    unsigned cnt_a  = s2u(&cnt[w]);
    unsigned cntp_a = s2u(&cnt[(w == 0) ? 15 : (w - 1)]);
    const int ispub = (lane == 31 && w < 7) ? 1 : 0;
    int cc = 0;
    const float* dxsrc = sdxp + 512 - i0;

    // pipelined up-neighbor (pre-renorm shfl of r1m1/r1s1 -- exact)
    float shm = __shfl_up_sync(0xFFFFFFFFu, r1m1, 1);
    float shs = __shfl_up_sync(0xFFFFFFFFu, r1s1, 1);

    #pragma unroll 1
    for (int d0 = lo; d0 <= hi; d0 += 4) {
        const int need = min(d0 + 3, cmax);
        if (cc < need) { do { cc = ld_acq(cntp_a); } while (cc < need); }

        // batched boundary fetch (clamped to producer's published range)
        const int dc = min(d0, clampv);
        const float4 bl0 = *reinterpret_cast<const float4*>(subrow + dc);
        const float4 bl1 = *reinterpret_cast<const float4*>(subrow + dc + 2);

        // dx prefetch for this block (8B-aligned: i0, d0 both even)
        const float2 fx0 = *reinterpret_cast<const float2*>(dxsrc + d0);
        const float2 fx1 = *reinterpret_cast<const float2*>(dxsrc + d0 + 2);

        #pragma unroll
        for (int u = 0; u < 4; ++u) {
            const int d = d0 + u;
            const float um = (lane == 0) ? mbm : shm;
            const float us = (lane == 0) ? mbs : shs;

            // CELL1 first: independent of um -> its output shfls immediately
            float nm0, ns0, nm1, ns1;
            CELL(nm1, ns1, r2m0, r2s0, r1m0, r1s0, r1m1, r1s1, dyr1, dxw1)
            shm = __shfl_up_sync(0xFFFFFFFFu, nm1, 1);   // pre-renorm: exact
            shs = __shfl_up_sync(0xFFFFFFFFu, ns1, 1);

            CELL(nm0, ns0, tn2m, tn2s, um,   us,   r1m0, r1s0, dyr0, dxw0)

            if (u == 3) {   // exact power-of-2 renorm of s into m (local only)
                unsigned sb0 = __float_as_uint(ns0);
                int e0 = (int)(sb0 >> 23) - 127;
                ns0 = __uint_as_float((sb0 & 0x007FFFFFu) | 0x3F800000u);
                nm0 -= (float)e0;
                unsigned sb1 = __float_as_uint(ns1);
                int e1 = (int)(sb1 >> 23) - 127;
                ns1 = __uint_as_float((sb1 & 0x007FFFFFu) | 0x3F800000u);
                nm1 -= (float)e1;
            }

            if (u == 0) sts_pair_pred_off<0 >(pub_a, nm1, ns1, ispub);
            if (u == 1) sts_pair_pred_off<8 >(pub_a, nm1, ns1, ispub);
            if (u == 2) sts_pair_pred_off<16>(pub_a, nm1, ns1, ispub);
            if (u == 3) sts_pair_pred_off<24>(pub_a, nm1, ns1, ispub);
            if (u == 3) strel_pred(cnt_a, d, ispub);

            tn2m = um;  tn2s = us;
            r2m0 = r1m0; r2s0 = r1s0;
            r1m0 = nm0;  r1s0 = ns0;  r1m1 = nm1;  r1s1 = ns1;
            dxw1 = dxw0;
            dxw0 = (u == 0) ? fx0.x : (u == 1) ? fx0.y : (u == 2) ? fx1.x : fx1.y;
            mbm = (u == 0) ? bl0.x : (u == 1) ? bl0.z : (u == 2) ? bl1.x : bl1.z;
            mbs = (u == 0) ? bl0.y : (u == 1) ? bl0.w : (u == 2) ? bl1.y : bl1.w;
        }
        pub_a += 32u;
    }

    // tail step d = 1022 — only warp 7 (row 511 result)
    if (w == 7) {
        const float um = (lane == 0) ? mbm : shm;
        const float us = (lane == 0) ? mbs : shs;
        float nm1, ns1;
        CELL(nm1, ns1, r2m0, r2s0, r1m0, r1s0, r1m1, r1s1, dyr1, dxw1)
        (void)um; (void)us;

        if (t == NT - 1) {                      // row 511 holds R[511,511]
            g_partial[b] = (nm1 - lg2f(ns1)) * INVK;
            __threadfence();
            int prev = atomicAdd(&g_done, 1);
            slast = (prev == NBATCH - 1) ? 1 : 0;
        }
    }
    __syncthreads();
    if (slast && t < 32) {
        __threadfence();
        float s = g_partial[t] + g_partial[t + 32];
        #pragma unroll
        for (int o = 16; o > 0; o >>= 1)
            s += __shfl_down_sync(0xFFFFFFFFu, s, o);
        if (t == 0) { out[0] = s * (1.0f / (float)NBATCH); g_done = 0; }
    }
}

extern "C" void kernel_launch(void* const* d_in, const int* in_sizes, int n_in,
                              void* d_out, int out_size)
{
    const float* input  = (const float*)d_in[0];
    const float* target = (const float*)d_in[1];
    float* out = (float*)d_out;

    cudaFuncSetAttribute(sdtw_kernel,
                         cudaFuncAttributeMaxDynamicSharedMemorySize, SMEM_BYTES);
    sdtw_kernel<<<NBATCH, NT, SMEM_BYTES>>>(input, target, out);
}